// round 14
// baseline (speedup 1.0000x reference)
#include <cuda_runtime.h>
#include <cuda_bf16.h>
#include <cstdint>

#define M_DIM 4096
#define K_DIM 4096
#define N_DIM 11008
#define NG    32          // K/128 groups

#define BM 128
#define BN 256
#define BK 64             // 64 bf16 = 128 B = one swizzled row-block
#define KTILES (K_DIM / BK)   // 64
#define STAGES 4
#define GTHREADS 256      // 8 warps: 2 (m) x 4 (n), warp tile 64x64
#define NTILES  ((M_DIM / BM) * (N_DIM / BN))   // 32*43 = 1376
#define NSM     148

// Scratch in TILE-CONTIGUOUS PRE-SWIZZLED layout:
//   block index = kt*ROWS + row ; each block = 128 B holding 64 bf16 (k-slice)
//   within block: chunk kc (16B) at offset ((kc ^ (row&7)) << 4)
__device__ __nv_bfloat16 g_X2[(size_t)M_DIM * K_DIM];
__device__ __nv_bfloat16 g_W2[(size_t)N_DIM * K_DIM];

// ---------------------------------------------------------------------------
#define MBARRIER_INIT(addr, cnt) \
    asm volatile("mbarrier.init.shared.b64 [%0], %1;" :: "r"(addr), "r"(cnt) : "memory")
#define MBARRIER_EXPECT_TX(addr, bytes) \
    asm volatile("mbarrier.arrive.expect_tx.shared.b64 _, [%0], %1;" :: "r"(addr), "r"(bytes) : "memory")
#define MBARRIER_ARRIVE(addr) \
    asm volatile("mbarrier.arrive.shared.b64 _, [%0];" :: "r"(addr) : "memory")

__device__ __forceinline__ void mbar_wait(uint32_t mbar, int parity) {
    asm volatile(
        "{\n\t.reg .pred P;\n"
        "W_%=:\n\t"
        "mbarrier.try_wait.parity.acquire.cta.shared::cta.b64 P, [%0], %1, 0x989680;\n\t"
        "@!P bra W_%=;\n\t}"
        :: "r"(mbar), "r"((uint32_t)parity) : "memory");
}

__device__ __forceinline__ void bulk_g2s(uint32_t sdst, const void* gsrc,
                                         uint32_t bytes, uint32_t mbar) {
    asm volatile(
        "cp.async.bulk.shared::cta.global.mbarrier::complete_tx::bytes [%0], [%1], %2, [%3];"
        :: "r"(sdst), "l"(gsrc), "r"(bytes), "r"(mbar) : "memory");
}

// ---------------------------------------------------------------------------
// Kernel 0: x f32 -> bf16 into tiled/swizzled g_X2 (1 thread = one 16B chunk)
// ---------------------------------------------------------------------------
__global__ void convert_x_kernel(const float* __restrict__ x) {
    uint32_t tid = blockIdx.x * blockDim.x + threadIdx.x;
    uint32_t kc = tid & 7;
    uint32_t rb = tid >> 3;           // kt*4096 + m
    uint32_t m  = rb & 4095;
    uint32_t kt = rb >> 12;
    const float4* src = reinterpret_cast<const float4*>(
        x + (size_t)m * K_DIM + (size_t)kt * 64 + kc * 8);
    float4 f0 = src[0], f1 = src[1];
    __align__(16) __nv_bfloat16 v[8];
    v[0] = __float2bfloat16(f0.x); v[1] = __float2bfloat16(f0.y);
    v[2] = __float2bfloat16(f0.z); v[3] = __float2bfloat16(f0.w);
    v[4] = __float2bfloat16(f1.x); v[5] = __float2bfloat16(f1.y);
    v[6] = __float2bfloat16(f1.z); v[7] = __float2bfloat16(f1.w);
    size_t dst = (size_t)rb * 128 + ((kc ^ (m & 7)) << 4);
    *reinterpret_cast<uint4*>((char*)g_X2 + dst) = *reinterpret_cast<const uint4*>(v);
}

// ---------------------------------------------------------------------------
// Kernel 1: dequant int32 -> bf16 into tiled/swizzled g_W2
//   w = bf16( bf16((q-8)*s) + z )
// ---------------------------------------------------------------------------
__global__ void dequant_kernel(const int* __restrict__ Wq,
                               const float* __restrict__ scales,
                               const float* __restrict__ zeros) {
    uint32_t tid = blockIdx.x * blockDim.x + threadIdx.x;
    uint32_t kc = tid & 7;
    uint32_t rb = tid >> 3;           // kt*11008 + n
    uint32_t n  = rb % 11008u;
    uint32_t kt = rb / 11008u;
    uint32_t g  = kt >> 1;            // (kt*64)/128
    float s = scales[(size_t)n * NG + g];
    float z = zeros [(size_t)n * NG + g];
    const int4* p = reinterpret_cast<const int4*>(
        Wq + (size_t)n * K_DIM + (size_t)kt * 64 + kc * 8);
    int4 q0 = p[0], q1 = p[1];
    int qs[8] = {q0.x, q0.y, q0.z, q0.w, q1.x, q1.y, q1.z, q1.w};
    __align__(16) __nv_bfloat16 v[8];
#pragma unroll
    for (int i = 0; i < 8; i++) {
        float t  = (float)qs[i] - 8.0f;
        float mf = __bfloat162float(__float2bfloat16(t * s));
        v[i]     = __float2bfloat16(mf + z);
    }
    size_t dst = (size_t)rb * 128 + ((kc ^ (n & 7)) << 4);
    *reinterpret_cast<uint4*>((char*)g_W2 + dst) = *reinterpret_cast<const uint4*>(v);
}

// ---------------------------------------------------------------------------
// Kernel 2: PERSISTENT mma.sync GEMM. grid=148, CTA 128x256, 8 warps @64x64.
// Flat work sequence q=(tile,kt); bulk pipeline + register fragment pipeline
// run continuously across output-tile boundaries.
// ---------------------------------------------------------------------------
#define SM_CTRL     1024
#define STAGE_BYTES 49152u          // A 16KB + B 32KB
#define B_OFF       16384u
#define SMEM_TOTAL  (SM_CTRL + STAGES * STAGE_BYTES)   // 197632

__device__ __forceinline__ uint32_t swz(uint32_t row, uint32_t kchunk) {
    return row * 128u + ((kchunk ^ (row & 7u)) << 4);
}

__device__ __forceinline__ void load_frags(uint32_t sa, uint32_t sb, int kk,
                                           int wm, int wn, int lane,
                                           uint32_t a[4][4], uint32_t b[8][2]) {
    const int kc = 2 * kk + (lane >> 4);
#pragma unroll
    for (int im = 0; im < 4; im++) {
        int mrow = wm * 64 + im * 16 + (lane & 15);
        uint32_t addr = sa + swz((uint32_t)mrow, (uint32_t)kc);
        asm volatile(
            "ldmatrix.sync.aligned.m8n8.x4.shared.b16 {%0,%1,%2,%3}, [%4];"
            : "=r"(a[im][0]), "=r"(a[im][1]), "=r"(a[im][2]), "=r"(a[im][3])
            : "r"(addr));
    }
#pragma unroll
    for (int in2 = 0; in2 < 4; in2++) {
        int nrow = wn * 64 + in2 * 16 + (lane & 15);
        uint32_t addr = sb + swz((uint32_t)nrow, (uint32_t)kc);
        uint32_t r0, r1, r2, r3;
        asm volatile(
            "ldmatrix.sync.aligned.m8n8.x4.shared.b16 {%0,%1,%2,%3}, [%4];"
            : "=r"(r0), "=r"(r1), "=r"(r2), "=r"(r3)
            : "r"(addr));
        b[in2 * 2 + 0][0] = r0; b[in2 * 2 + 0][1] = r2;
        b[in2 * 2 + 1][0] = r1; b[in2 * 2 + 1][1] = r3;
    }
}

__global__ void __launch_bounds__(GTHREADS, 1)
gemm_hmma_kernel(float* __restrict__ C) {
    extern __shared__ __align__(1024) uint8_t smem[];
    const uint32_t sbase = (uint32_t)__cvta_generic_to_shared(smem);

    const int tid  = threadIdx.x;
    const int lane = tid & 31;
    const int warp = tid >> 5;      // 0..7
    const int wm   = warp >> 2;     // 0..1
    const int wn   = warp & 3;      // 0..3
    const int bid  = blockIdx.x;    // 0..147

    const int nmine = (NTILES - bid + NSM - 1) / NSM;   // 9 or 10
    const int W = nmine * KTILES;                        // flat work items

    if (tid == 0) {
#pragma unroll
        for (int s = 0; s < STAGES; s++) {
            MBARRIER_INIT(sbase + 64 + s * 16,     1);   // full (tx)
            MBARRIER_INIT(sbase + 64 + s * 16 + 8, 8);   // empty (8 warps)
        }
        asm volatile("fence.proxy.async.shared::cta;" ::: "memory");
    }
    __syncthreads();

    auto issue = [&](int q) {
        int t  = bid + NSM * (q >> 6);        // output tile index
        int kt = q & 63;
        int tbm = t & 31, tbn = t >> 5;
        const char* a = (const char*)g_X2 + ((size_t)tbm * BM) * 128
                        + (size_t)kt * M_DIM * 128;
        const char* b = (const char*)g_W2 + ((size_t)tbn * BN) * 128
                        + (size_t)kt * N_DIM * 128;
        int s = q & 3;
        uint32_t fm = sbase + 64 + s * 16;
        uint32_t sd = sbase + SM_CTRL + (uint32_t)s * STAGE_BYTES;
        MBARRIER_EXPECT_TX(fm, STAGE_BYTES);
        bulk_g2s(sd,         a, 16384, fm);
        bulk_g2s(sd + B_OFF, b, 32768, fm);
    };

    if (tid == 0) {
        issue(0); issue(1); issue(2); issue(3);
    }

    float acc[4][8][4];
#pragma unroll
    for (int i = 0; i < 4; i++)
#pragma unroll
        for (int j = 0; j < 8; j++)
#pragma unroll
            for (int r = 0; r < 4; r++) acc[i][j][r] = 0.0f;

    uint32_t abuf[2][4][4];
    uint32_t bbuf[2][8][2];

    // prologue: wait work 0, load kk=0 fragments
    mbar_wait(sbase + 64, 0);
    {
        uint32_t sa = sbase + SM_CTRL;
        load_frags(sa, sa + B_OFF, 0, wm, wn, lane, abuf[0], bbuf[0]);
    }

    for (int q = 0; q < W; q++) {
        const int s = q & 3;
        const uint32_t sa = sbase + SM_CTRL + (uint32_t)s * STAGE_BYTES;
        const uint32_t sb = sa + B_OFF;

#pragma unroll
        for (int kk = 0; kk < 4; kk++) {
            const int cb = kk & 1;
            const int nb = cb ^ 1;

            if (kk < 3) {
                load_frags(sa, sb, kk + 1, wm, wn, lane, abuf[nb], bbuf[nb]);
            } else if (q + 1 < W) {
                const int s2 = (q + 1) & 3;
                mbar_wait(sbase + 64 + s2 * 16, ((q + 1) >> 2) & 1);
                uint32_t sa2 = sbase + SM_CTRL + (uint32_t)s2 * STAGE_BYTES;
                load_frags(sa2, sa2 + B_OFF, 0, wm, wn, lane, abuf[nb], bbuf[nb]);
            }

#pragma unroll
            for (int im = 0; im < 4; im++)
#pragma unroll
                for (int in = 0; in < 8; in++) {
                    asm volatile(
                        "mma.sync.aligned.m16n8k16.row.col.f32.bf16.bf16.f32 "
                        "{%0,%1,%2,%3}, {%4,%5,%6,%7}, {%8,%9}, {%0,%1,%2,%3};\n"
                        : "+f"(acc[im][in][0]), "+f"(acc[im][in][1]),
                          "+f"(acc[im][in][2]), "+f"(acc[im][in][3])
                        : "r"(abuf[cb][im][0]), "r"(abuf[cb][im][1]),
                          "r"(abuf[cb][im][2]), "r"(abuf[cb][im][3]),
                          "r"(bbuf[cb][in][0]), "r"(bbuf[cb][in][1]));
                }
        }

        if (lane == 0) MBARRIER_ARRIVE(sbase + 64 + s * 16 + 8);

        if (tid == 0) {
            int t = q + 4;
            if (t < W) {
                mbar_wait(sbase + 64 + (t & 3) * 16 + 8, ((t >> 2) + 1) & 1);
                issue(t);
            }
        }

        if ((q & 63) == 63) {
            // epilogue for the tile just finished; pipeline keeps running
            int tl   = bid + NSM * (q >> 6);
            int row0 = (tl & 31) * BM + wm * 64;
            int col0 = (tl >> 5) * BN + wn * 64;
#pragma unroll
            for (int im = 0; im < 4; im++) {
#pragma unroll
                for (int in = 0; in < 8; in++) {
                    int r = row0 + im * 16 + (lane >> 2);
                    int c = col0 + in * 8 + (lane & 3) * 2;
                    float2 v0, v1;
                    v0.x = __bfloat162float(__float2bfloat16(acc[im][in][0]));
                    v0.y = __bfloat162float(__float2bfloat16(acc[im][in][1]));
                    v1.x = __bfloat162float(__float2bfloat16(acc[im][in][2]));
                    v1.y = __bfloat162float(__float2bfloat16(acc[im][in][3]));
                    *reinterpret_cast<float2*>(C + (size_t)r * N_DIM + c) = v0;
                    *reinterpret_cast<float2*>(C + (size_t)(r + 8) * N_DIM + c) = v1;
                    acc[im][in][0] = 0.0f; acc[im][in][1] = 0.0f;
                    acc[im][in][2] = 0.0f; acc[im][in][3] = 0.0f;
                }
            }
        }
    }
}

// ---------------------------------------------------------------------------
extern "C" void kernel_launch(void* const* d_in, const int* in_sizes, int n_in,
                              void* d_out, int out_size) {
    // All "bf16" tensors are materialized as FLOAT32 buffers (decoded R1-R8)
    const float* x      = (const float*)d_in[0];   // [4096, 4096]  f32
    const int*   Wq     = (const int*)d_in[1];     // [11008, 4096] int32
    const float* scales = (const float*)d_in[2];   // [11008, 32]   f32
    const float* zeros  = (const float*)d_in[3];   // [11008, 32]   f32
    float*       out    = (float*)d_out;           // [4096, 11008] f32

    convert_x_kernel<<<8192, 256>>>(x);
    dequant_kernel<<<22016, 256>>>(Wq, scales, zeros);

    cudaFuncSetAttribute(gemm_hmma_kernel,
                         cudaFuncAttributeMaxDynamicSharedMemorySize, SMEM_TOTAL);
    gemm_hmma_kernel<<<NSM, GTHREADS, SMEM_TOTAL>>>(out);
}

// round 15
// speedup vs baseline: 1.7562x; 1.7562x over previous
#include <cuda_runtime.h>
#include <cuda_bf16.h>
#include <cstdint>

#define M_DIM 4096
#define K_DIM 4096
#define N_DIM 11008
#define NG    32          // K/128 groups

#define BM 128
#define BN 256
#define BK 64             // 64 bf16 = 128 B = one swizzled row-block
#define KTILES (K_DIM / BK)   // 64
#define STAGES 4
#define GTHREADS 256      // 8 warps: 2 (m) x 4 (n), warp tile 64x64

// Scratch in TILE-CONTIGUOUS PRE-SWIZZLED layout:
//   block index = kt*ROWS + row ; each block = 128 B holding 64 bf16 (k-slice)
//   within block: chunk kc (16B) at offset ((kc ^ (row&7)) << 4)
__device__ __nv_bfloat16 g_X2[(size_t)M_DIM * K_DIM];
__device__ __nv_bfloat16 g_W2[(size_t)N_DIM * K_DIM];

// ---------------------------------------------------------------------------
#define MBARRIER_INIT(addr, cnt) \
    asm volatile("mbarrier.init.shared.b64 [%0], %1;" :: "r"(addr), "r"(cnt) : "memory")
#define MBARRIER_EXPECT_TX(addr, bytes) \
    asm volatile("mbarrier.arrive.expect_tx.shared.b64 _, [%0], %1;" :: "r"(addr), "r"(bytes) : "memory")
#define MBARRIER_ARRIVE(addr) \
    asm volatile("mbarrier.arrive.shared.b64 _, [%0];" :: "r"(addr) : "memory")

__device__ __forceinline__ void mbar_wait(uint32_t mbar, int parity) {
    asm volatile(
        "{\n\t.reg .pred P;\n"
        "W_%=:\n\t"
        "mbarrier.try_wait.parity.acquire.cta.shared::cta.b64 P, [%0], %1, 0x989680;\n\t"
        "@!P bra W_%=;\n\t}"
        :: "r"(mbar), "r"((uint32_t)parity) : "memory");
}

__device__ __forceinline__ void bulk_g2s(uint32_t sdst, const void* gsrc,
                                         uint32_t bytes, uint32_t mbar) {
    asm volatile(
        "cp.async.bulk.shared::cta.global.mbarrier::complete_tx::bytes [%0], [%1], %2, [%3];"
        :: "r"(sdst), "l"(gsrc), "r"(bytes), "r"(mbar) : "memory");
}

// ---------------------------------------------------------------------------
// Kernel 0+1 merged: blocks [0,8192) convert x f32->bf16 into g_X2;
// blocks [8192,30208) dequant Wq into g_W2. Both tiled/pre-swizzled.
// ---------------------------------------------------------------------------
#define XBLOCKS 8192u
#define PREBLOCKS (8192u + 22016u)

__global__ void prepass_kernel(const float* __restrict__ x,
                               const int* __restrict__ Wq,
                               const float* __restrict__ scales,
                               const float* __restrict__ zeros) {
    if (blockIdx.x < XBLOCKS) {
        uint32_t tid = blockIdx.x * 256 + threadIdx.x;
        uint32_t kc = tid & 7;
        uint32_t rb = tid >> 3;           // kt*4096 + m
        uint32_t m  = rb & 4095;
        uint32_t kt = rb >> 12;
        const float4* src = reinterpret_cast<const float4*>(
            x + (size_t)m * K_DIM + (size_t)kt * 64 + kc * 8);
        float4 f0 = src[0], f1 = src[1];
        __align__(16) __nv_bfloat16 v[8];
        v[0] = __float2bfloat16(f0.x); v[1] = __float2bfloat16(f0.y);
        v[2] = __float2bfloat16(f0.z); v[3] = __float2bfloat16(f0.w);
        v[4] = __float2bfloat16(f1.x); v[5] = __float2bfloat16(f1.y);
        v[6] = __float2bfloat16(f1.z); v[7] = __float2bfloat16(f1.w);
        size_t dst = (size_t)rb * 128 + ((kc ^ (m & 7)) << 4);
        *reinterpret_cast<uint4*>((char*)g_X2 + dst) =
            *reinterpret_cast<const uint4*>(v);
    } else {
        uint32_t tid = (blockIdx.x - XBLOCKS) * 256 + threadIdx.x;
        uint32_t kc = tid & 7;
        uint32_t rb = tid >> 3;           // kt*11008 + n
        uint32_t n  = rb % 11008u;
        uint32_t kt = rb / 11008u;
        uint32_t g  = kt >> 1;            // (kt*64)/128
        float s = scales[(size_t)n * NG + g];
        float z = zeros [(size_t)n * NG + g];
        const int4* p = reinterpret_cast<const int4*>(
            Wq + (size_t)n * K_DIM + (size_t)kt * 64 + kc * 8);
        int4 q0 = p[0], q1 = p[1];
        int qs[8] = {q0.x, q0.y, q0.z, q0.w, q1.x, q1.y, q1.z, q1.w};
        __align__(16) __nv_bfloat16 v[8];
#pragma unroll
        for (int i = 0; i < 8; i++) {
            float t  = (float)qs[i] - 8.0f;
            float mf = __bfloat162float(__float2bfloat16(t * s));
            v[i]     = __float2bfloat16(mf + z);
        }
        size_t dst = (size_t)rb * 128 + ((kc ^ (n & 7)) << 4);
        *reinterpret_cast<uint4*>((char*)g_W2 + dst) =
            *reinterpret_cast<const uint4*>(v);
    }
}

// ---------------------------------------------------------------------------
// Kernel 2: mma.sync GEMM, CTA 128x256, 8 warps @ 64x64, 4-stage bulk pipe,
// register-double-buffered fragments (R13 verbatim — known 835 us).
// ---------------------------------------------------------------------------
#define SM_CTRL     1024
#define STAGE_BYTES 49152u          // A 16KB + B 32KB
#define B_OFF       16384u
#define SMEM_TOTAL  (SM_CTRL + STAGES * STAGE_BYTES)   // 197632

__device__ __forceinline__ uint32_t swz(uint32_t row, uint32_t kchunk) {
    return row * 128u + ((kchunk ^ (row & 7u)) << 4);
}

__device__ __forceinline__ void load_frags(uint32_t sa, uint32_t sb, int kk,
                                           int wm, int wn, int lane,
                                           uint32_t a[4][4], uint32_t b[8][2]) {
    const int kc = 2 * kk + (lane >> 4);
#pragma unroll
    for (int im = 0; im < 4; im++) {
        int mrow = wm * 64 + im * 16 + (lane & 15);
        uint32_t addr = sa + swz((uint32_t)mrow, (uint32_t)kc);
        asm volatile(
            "ldmatrix.sync.aligned.m8n8.x4.shared.b16 {%0,%1,%2,%3}, [%4];"
            : "=r"(a[im][0]), "=r"(a[im][1]), "=r"(a[im][2]), "=r"(a[im][3])
            : "r"(addr));
    }
#pragma unroll
    for (int in2 = 0; in2 < 4; in2++) {
        int nrow = wn * 64 + in2 * 16 + (lane & 15);
        uint32_t addr = sb + swz((uint32_t)nrow, (uint32_t)kc);
        uint32_t r0, r1, r2, r3;
        asm volatile(
            "ldmatrix.sync.aligned.m8n8.x4.shared.b16 {%0,%1,%2,%3}, [%4];"
            : "=r"(r0), "=r"(r1), "=r"(r2), "=r"(r3)
            : "r"(addr));
        b[in2 * 2 + 0][0] = r0; b[in2 * 2 + 0][1] = r2;
        b[in2 * 2 + 1][0] = r1; b[in2 * 2 + 1][1] = r3;
    }
}

__global__ void __launch_bounds__(GTHREADS, 1)
gemm_hmma_kernel(float* __restrict__ C) {
    extern __shared__ __align__(1024) uint8_t smem[];
    const uint32_t sbase = (uint32_t)__cvta_generic_to_shared(smem);

    const int tid  = threadIdx.x;
    const int lane = tid & 31;
    const int warp = tid >> 5;      // 0..7
    const int wm   = warp >> 2;     // 0..1
    const int wn   = warp & 3;      // 0..3

    const int bm = blockIdx.x;      // 0..31
    const int bn = blockIdx.y;      // 0..42

    // full[s] at 64+s*16 (tx), empty[s] at 64+s*16+8 (count=8 warps)
    if (tid == 0) {
#pragma unroll
        for (int s = 0; s < STAGES; s++) {
            MBARRIER_INIT(sbase + 64 + s * 16,     1);
            MBARRIER_INIT(sbase + 64 + s * 16 + 8, 8);
        }
        asm volatile("fence.proxy.async.shared::cta;" ::: "memory");
    }
    __syncthreads();

    const char* gA = (const char*)g_X2 + ((size_t)bm * BM) * 128;
    const char* gB = (const char*)g_W2 + ((size_t)bn * BN) * 128;

    auto issue_stage = [&](int s, int kt) {
        uint32_t fm = sbase + 64 + s * 16;
        uint32_t sd = sbase + SM_CTRL + (uint32_t)s * STAGE_BYTES;
        MBARRIER_EXPECT_TX(fm, STAGE_BYTES);
        bulk_g2s(sd,         gA + (size_t)kt * M_DIM * 128, 16384, fm);
        bulk_g2s(sd + B_OFF, gB + (size_t)kt * N_DIM * 128, 32768, fm);
    };

    if (tid == 0) {
        issue_stage(0, 0); issue_stage(1, 1);
        issue_stage(2, 2); issue_stage(3, 3);
    }

    float acc[4][8][4];
#pragma unroll
    for (int i = 0; i < 4; i++)
#pragma unroll
        for (int j = 0; j < 8; j++)
#pragma unroll
            for (int r = 0; r < 4; r++) acc[i][j][r] = 0.0f;

    uint32_t abuf[2][4][4];
    uint32_t bbuf[2][8][2];

    // prologue: wait tile 0, load its kk=0 fragments into buffer 0
    mbar_wait(sbase + 64 + 0 * 16, 0);
    {
        uint32_t sa = sbase + SM_CTRL;
        load_frags(sa, sa + B_OFF, 0, wm, wn, lane, abuf[0], bbuf[0]);
    }

    for (int kt = 0; kt < KTILES; kt++) {
        const int s = kt & 3;
        const uint32_t sa = sbase + SM_CTRL + (uint32_t)s * STAGE_BYTES;
        const uint32_t sb = sa + B_OFF;

#pragma unroll
        for (int kk = 0; kk < 4; kk++) {
            const int cb = kk & 1;          // current buffer
            const int nb = cb ^ 1;          // next buffer

            if (kk < 3) {
                load_frags(sa, sb, kk + 1, wm, wn, lane, abuf[nb], bbuf[nb]);
            } else if (kt + 1 < KTILES) {
                const int s2 = (kt + 1) & 3;
                mbar_wait(sbase + 64 + s2 * 16, ((kt + 1) >> 2) & 1);
                uint32_t sa2 = sbase + SM_CTRL + (uint32_t)s2 * STAGE_BYTES;
                load_frags(sa2, sa2 + B_OFF, 0, wm, wn, lane, abuf[nb], bbuf[nb]);
            }

#pragma unroll
            for (int im = 0; im < 4; im++)
#pragma unroll
                for (int in = 0; in < 8; in++) {
                    asm volatile(
                        "mma.sync.aligned.m16n8k16.row.col.f32.bf16.bf16.f32 "
                        "{%0,%1,%2,%3}, {%4,%5,%6,%7}, {%8,%9}, {%0,%1,%2,%3};\n"
                        : "+f"(acc[im][in][0]), "+f"(acc[im][in][1]),
                          "+f"(acc[im][in][2]), "+f"(acc[im][in][3])
                        : "r"(abuf[cb][im][0]), "r"(abuf[cb][im][1]),
                          "r"(abuf[cb][im][2]), "r"(abuf[cb][im][3]),
                          "r"(bbuf[cb][in][0]), "r"(bbuf[cb][in][1]));
                }
        }

        if (lane == 0) MBARRIER_ARRIVE(sbase + 64 + s * 16 + 8);   // warp done

        if (tid == 0) {
            int t = kt + 4;
            if (t < KTILES) {
                mbar_wait(sbase + 64 + (t & 3) * 16 + 8, (kt >> 2) & 1);
                issue_stage(t & 3, t);
            }
        }
    }

    // epilogue: f32 output of bf16-rounded accumulators
    const int row0 = bm * BM + wm * 64;
    const int col0 = bn * BN + wn * 64;
#pragma unroll
    for (int im = 0; im < 4; im++) {
#pragma unroll
        for (int in = 0; in < 8; in++) {
            int r = row0 + im * 16 + (lane >> 2);
            int c = col0 + in * 8 + (lane & 3) * 2;
            float2 v0, v1;
            v0.x = __bfloat162float(__float2bfloat16(acc[im][in][0]));
            v0.y = __bfloat162float(__float2bfloat16(acc[im][in][1]));
            v1.x = __bfloat162float(__float2bfloat16(acc[im][in][2]));
            v1.y = __bfloat162float(__float2bfloat16(acc[im][in][3]));
            *reinterpret_cast<float2*>(C + (size_t)r * N_DIM + c) = v0;
            *reinterpret_cast<float2*>(C + (size_t)(r + 8) * N_DIM + c) = v1;
        }
    }
}

// ---------------------------------------------------------------------------
extern "C" void kernel_launch(void* const* d_in, const int* in_sizes, int n_in,
                              void* d_out, int out_size) {
    // All "bf16" tensors are materialized as FLOAT32 buffers (decoded R1-R8)
    const float* x      = (const float*)d_in[0];   // [4096, 4096]  f32
    const int*   Wq     = (const int*)d_in[1];     // [11008, 4096] int32
    const float* scales = (const float*)d_in[2];   // [11008, 32]   f32
    const float* zeros  = (const float*)d_in[3];   // [11008, 32]   f32
    float*       out    = (float*)d_out;           // [4096, 11008] f32

    prepass_kernel<<<PREBLOCKS, 256>>>(x, Wq, scales, zeros);

    cudaFuncSetAttribute(gemm_hmma_kernel,
                         cudaFuncAttributeMaxDynamicSharedMemorySize, SMEM_TOTAL);
    dim3 grid(M_DIM / BM, N_DIM / BN);   // 32 x 43
    gemm_hmma_kernel<<<grid, GTHREADS, SMEM_TOTAL>>>(out);
}